// round 12
// baseline (speedup 1.0000x reference)
#include <cuda_runtime.h>
#include <float.h>

// Problem constants (from reference)
#define B_      8
#define L_      2048
#define D_      256
#define T_      32
#define S_PARA  8
#define S_ADU   24
#define S_SHELL 24

#define D4      (D_ / 4)          // 64 float4 lanes per row
#define ROWS_TOPIC  (B_)                  // 8
#define ROWS_PARA   (B_ * S_PARA)         // 64
#define ROWS_SHELL  (B_ * S_SHELL)        // 192
#define ROWS_ADU    (B_ * S_ADU)          // 192
#define ROWS_TOTAL  (ROWS_TOPIC + ROWS_PARA + ROWS_SHELL + ROWS_ADU)  // 456

// flat output offsets (float elements), reference return order:
// (topic_out, para_reps, span_reps<-shell, adu_reps<-x)
#define OFF_TOPIC 0
#define OFF_PARA  (B_ * D_)                              // 2048
#define OFF_SHELL (OFF_PARA + B_ * S_PARA * D_)          // 18432
#define OFF_ADU   (OFF_SHELL + B_ * S_SHELL * D_)        // 67584

#define YS 4   // span-dimension split per block

__device__ __forceinline__ float4 f4max(float4 a, float4 b) {
    float4 r;
    r.x = fmaxf(a.x, b.x);
    r.y = fmaxf(a.y, b.y);
    r.z = fmaxf(a.z, b.z);
    r.w = fmaxf(a.w, b.w);
    return r;
}

__global__ __launch_bounds__(64 * YS) void span_maxpool_kernel(
    const float* __restrict__ topic_reps,   // [B,T,D]
    const float* __restrict__ word_reps,    // [B,L,D]
    const int*   __restrict__ para_spans,   // [B,S_PARA,3]
    const int*   __restrict__ x_spans,      // [B,S_ADU,3]
    const int*   __restrict__ shell_spans,  // [B,S_SHELL,3]
    float*       __restrict__ out)
{
    __shared__ float4 red[YS][D4];          // 4 KB

    const int row  = blockIdx.x;            // 0..455 (one output row per block)
    const int lane = threadIdx.x;           // 0..63 (float4 lane across D)
    const int ys   = threadIdx.y;           // 0..3  (span-dim slice)

    const float4* src;   // base of first pooled row, at this lane
    int cnt;             // rows to pool (>=1)
    int out_off;         // flat float offset of output row

    if (row < ROWS_TOPIC) {
        src = (const float4*)(topic_reps + (size_t)row * T_ * D_) + lane;
        cnt = T_;
        out_off = OFF_TOPIC + row * D_;
    } else if (row < ROWS_TOPIC + ROWS_PARA) {
        const int i = row - ROWS_TOPIC;
        const int* sp = para_spans + i * 3;
        src = (const float4*)(word_reps + ((size_t)sp[0] * L_ + sp[1]) * D_) + lane;
        cnt = sp[2] - sp[1] + 1;
        out_off = OFF_PARA + i * D_;
    } else if (row < ROWS_TOPIC + ROWS_PARA + ROWS_SHELL) {
        const int i = row - (ROWS_TOPIC + ROWS_PARA);
        const int* sp = shell_spans + i * 3;
        src = (const float4*)(word_reps + ((size_t)sp[0] * L_ + sp[1]) * D_) + lane;
        cnt = sp[2] - sp[1] + 1;
        out_off = OFF_SHELL + i * D_;
    } else {
        const int i = row - (ROWS_TOPIC + ROWS_PARA + ROWS_SHELL);
        const int* sp = x_spans + i * 3;
        src = (const float4*)(word_reps + ((size_t)sp[0] * L_ + sp[1]) * D_) + lane;
        cnt = sp[2] - sp[1] + 1;
        out_off = OFF_ADU + i * D_;
    }

    float4 acc = make_float4(-FLT_MAX, -FLT_MAX, -FLT_MAX, -FLT_MAX);

    // Each y-slice pools rows i = ys, ys+YS, ys+2*YS, ...
    // Manual 4x unroll -> up to 4 independent loads in flight per thread.
    int i = ys;
    for (; i + 3 * YS < cnt; i += 4 * YS) {
        float4 v0 = __ldg(src + (size_t)(i + 0 * YS) * D4);
        float4 v1 = __ldg(src + (size_t)(i + 1 * YS) * D4);
        float4 v2 = __ldg(src + (size_t)(i + 2 * YS) * D4);
        float4 v3 = __ldg(src + (size_t)(i + 3 * YS) * D4);
        acc = f4max(acc, f4max(f4max(v0, v1), f4max(v2, v3)));
    }
    for (; i < cnt; i += YS) {
        acc = f4max(acc, __ldg(src + (size_t)i * D4));
    }

    red[ys][lane] = acc;
    __syncthreads();

    if (ys == 0) {
        float4 r = f4max(f4max(red[0][lane], red[1][lane]),
                         f4max(red[2][lane], red[3][lane]));
        ((float4*)(out + out_off))[lane] = r;
    }
}

extern "C" void kernel_launch(void* const* d_in, const int* in_sizes, int n_in,
                              void* d_out, int out_size) {
    // metadata order: topic_reps, word_reps, topic_lens(int64, unused),
    //                 para_spans, x_spans, shell_spans
    const float* topic_reps  = (const float*)d_in[0];
    const float* word_reps   = (const float*)d_in[1];
    const int*   para_spans  = (const int*)d_in[3];
    const int*   x_spans     = (const int*)d_in[4];
    const int*   shell_spans = (const int*)d_in[5];
    float* out = (float*)d_out;

    dim3 block(64, YS);        // 256 threads
    dim3 grid(ROWS_TOTAL);     // 456 blocks, one per output row
    span_maxpool_kernel<<<grid, block>>>(topic_reps, word_reps,
                                         para_spans, x_spans, shell_spans, out);
}

// round 13
// speedup vs baseline: 1.0370x; 1.0370x over previous
#include <cuda_runtime.h>
#include <float.h>

// Problem constants (from reference)
#define B_      8
#define L_      2048
#define D_      256
#define T_      32
#define S_PARA  8
#define S_ADU   24
#define S_SHELL 24

#define D4      (D_ / 4)          // 64 float4 columns per full row
#define HALF4   32                // 32 float4 columns per half-row
#define ROWS_TOPIC  (B_)                  // 8
#define ROWS_PARA   (B_ * S_PARA)         // 64
#define ROWS_SHELL  (B_ * S_SHELL)        // 192
#define ROWS_ADU    (B_ * S_ADU)          // 192
#define ROWS_TOTAL  (ROWS_TOPIC + ROWS_PARA + ROWS_SHELL + ROWS_ADU)  // 456

// flat output offsets (float elements), reference return order:
// (topic_out, para_reps, span_reps<-shell, adu_reps<-x)
#define OFF_TOPIC 0
#define OFF_PARA  (B_ * D_)                              // 2048
#define OFF_SHELL (OFF_PARA + B_ * S_PARA * D_)          // 18432
#define OFF_ADU   (OFF_SHELL + B_ * S_SHELL * D_)        // 67584

#define YS 8   // span-dimension slices per block (32 x 8 = 256 threads)

__device__ __forceinline__ float4 f4max(float4 a, float4 b) {
    float4 r;
    r.x = fmaxf(a.x, b.x);
    r.y = fmaxf(a.y, b.y);
    r.z = fmaxf(a.z, b.z);
    r.w = fmaxf(a.w, b.w);
    return r;
}

// Two blocks per output row (one per D-half). Block = 32 lanes x YS=8 slices.
// Zero atomics/fences/scratch; one barrier; para chain = 4 predicated 8-groups.
__global__ __launch_bounds__(32 * YS) void span_maxpool_dsplit_kernel(
    const float* __restrict__ topic_reps,   // [B,T,D]
    const float* __restrict__ word_reps,    // [B,L,D]
    const int*   __restrict__ para_spans,   // [B,S_PARA,3]
    const int*   __restrict__ x_spans,      // [B,S_ADU,3]
    const int*   __restrict__ shell_spans,  // [B,S_SHELL,3]
    float*       __restrict__ out)
{
    __shared__ float4 red[YS][HALF4];       // 4 KB

    const int row  = blockIdx.x >> 1;       // 0..455 output row
    const int half = blockIdx.x & 1;        // 0..1 D-half
    const int lx   = threadIdx.x;           // 0..31
    const int lane = half * HALF4 + lx;     // float4 column 0..63
    const int ys   = threadIdx.y;           // 0..7

    const float4* src;   // first pooled row, at this column
    int cnt;             // rows to pool (>=1)
    int out_off;         // flat float offset of output row (full row base)

    if (row < ROWS_TOPIC) {
        src = (const float4*)(topic_reps + (size_t)row * T_ * D_) + lane;
        cnt = T_;
        out_off = OFF_TOPIC + row * D_;
    } else if (row < ROWS_TOPIC + ROWS_PARA) {
        const int i = row - ROWS_TOPIC;
        const int* sp = para_spans + i * 3;
        src = (const float4*)(word_reps + ((size_t)sp[0] * L_ + sp[1]) * D_) + lane;
        cnt = sp[2] - sp[1] + 1;            // <= 256
        out_off = OFF_PARA + i * D_;
    } else if (row < ROWS_TOPIC + ROWS_PARA + ROWS_SHELL) {
        const int i = row - (ROWS_TOPIC + ROWS_PARA);
        const int* sp = shell_spans + i * 3;
        src = (const float4*)(word_reps + ((size_t)sp[0] * L_ + sp[1]) * D_) + lane;
        cnt = sp[2] - sp[1] + 1;            // <= 16
        out_off = OFF_SHELL + i * D_;
    } else {
        const int i = row - (ROWS_TOPIC + ROWS_PARA + ROWS_SHELL);
        const int* sp = x_spans + i * 3;
        src = (const float4*)(word_reps + ((size_t)sp[0] * L_ + sp[1]) * D_) + lane;
        cnt = sp[2] - sp[1] + 1;            // <= 64
        out_off = OFF_ADU + i * D_;
    }

    const float4 neg = make_float4(-FLT_MAX, -FLT_MAX, -FLT_MAX, -FLT_MAX);
    float4 acc = neg;

    // Slice ys pools rows ys, ys+8, ... in groups of 8 predicated independent
    // loads (64 rows/iteration). shell/topic/adu: 1 iter; para: <=4.
    #pragma unroll 1
    for (int r0 = ys; r0 < cnt; r0 += 8 * YS) {
        float4 v[8];
        #pragma unroll
        for (int j = 0; j < 8; j++) {
            const int r = r0 + j * YS;
            v[j] = (r < cnt) ? __ldg(src + (size_t)r * D4) : neg;
        }
        float4 a01 = f4max(v[0], v[1]);
        float4 a23 = f4max(v[2], v[3]);
        float4 a45 = f4max(v[4], v[5]);
        float4 a67 = f4max(v[6], v[7]);
        acc = f4max(acc, f4max(f4max(a01, a23), f4max(a45, a67)));
    }

    red[ys][lx] = acc;
    __syncthreads();                        // the only barrier

    if (ys == 0) {
        float4 r = f4max(f4max(f4max(red[0][lx], red[1][lx]),
                               f4max(red[2][lx], red[3][lx])),
                         f4max(f4max(red[4][lx], red[5][lx]),
                               f4max(red[6][lx], red[7][lx])));
        ((float4*)(out + out_off))[lane] = r;
    }
}

extern "C" void kernel_launch(void* const* d_in, const int* in_sizes, int n_in,
                              void* d_out, int out_size) {
    // metadata order: topic_reps, word_reps, topic_lens(int64, unused),
    //                 para_spans, x_spans, shell_spans
    const float* topic_reps  = (const float*)d_in[0];
    const float* word_reps   = (const float*)d_in[1];
    const int*   para_spans  = (const int*)d_in[3];
    const int*   x_spans     = (const int*)d_in[4];
    const int*   shell_spans = (const int*)d_in[5];
    float* out = (float*)d_out;

    dim3 block(32, YS);                // 256 threads
    dim3 grid(ROWS_TOTAL * 2);         // 912 blocks: (row, D-half)
    span_maxpool_dsplit_kernel<<<grid, block>>>(
        topic_reps, word_reps, para_spans, x_spans, shell_spans, out);
}

// round 14
// speedup vs baseline: 1.0566x; 1.0189x over previous
#include <cuda_runtime.h>
#include <float.h>

// Problem constants (from reference)
#define B_      8
#define L_      2048
#define D_      256
#define T_      32
#define S_PARA  8
#define S_ADU   24
#define S_SHELL 24

#define D4      (D_ / 4)          // 64 float4 columns per full row
#define HALF4   32                // 32 float4 columns per half-row
#define ROWS_TOPIC  (B_)                  // 8
#define ROWS_PARA   (B_ * S_PARA)         // 64
#define ROWS_SHELL  (B_ * S_SHELL)        // 192
#define ROWS_ADU    (B_ * S_ADU)          // 192
#define ROWS_TOTAL  (ROWS_TOPIC + ROWS_PARA + ROWS_SHELL + ROWS_ADU)  // 456

// flat output offsets (float elements), reference return order:
// (topic_out, para_reps, span_reps<-shell, adu_reps<-x)
#define OFF_TOPIC 0
#define OFF_PARA  (B_ * D_)                              // 2048
#define OFF_SHELL (OFF_PARA + B_ * S_PARA * D_)          // 18432
#define OFF_ADU   (OFF_SHELL + B_ * S_SHELL * D_)        // 67584

#define YS 8   // span-dimension slices per block (32 x 8 = 256 threads)

__device__ __forceinline__ float4 f4max(float4 a, float4 b) {
    float4 r;
    r.x = fmaxf(a.x, b.x);
    r.y = fmaxf(a.y, b.y);
    r.z = fmaxf(a.z, b.z);
    r.w = fmaxf(a.w, b.w);
    return r;
}

// Two blocks per output row (one per D-half). Block = 32 lanes x YS=8 slices.
// Zero atomics/fences/scratch; one barrier; para chain = 4 predicated 8-groups.
__global__ __launch_bounds__(32 * YS) void span_maxpool_dsplit_kernel(
    const float* __restrict__ topic_reps,   // [B,T,D]
    const float* __restrict__ word_reps,    // [B,L,D]
    const int*   __restrict__ para_spans,   // [B,S_PARA,3]
    const int*   __restrict__ x_spans,      // [B,S_ADU,3]
    const int*   __restrict__ shell_spans,  // [B,S_SHELL,3]
    float*       __restrict__ out)
{
    __shared__ float4 red[YS][HALF4];       // 4 KB

    const int row  = blockIdx.x >> 1;       // 0..455 output row
    const int half = blockIdx.x & 1;        // 0..1 D-half
    const int lx   = threadIdx.x;           // 0..31
    const int lane = half * HALF4 + lx;     // float4 column 0..63
    const int ys   = threadIdx.y;           // 0..7

    const float4* src;   // first pooled row, at this column
    int cnt;             // rows to pool (>=1)
    int out_off;         // flat float offset of output row (full row base)

    if (row < ROWS_TOPIC) {
        src = (const float4*)(topic_reps + (size_t)row * T_ * D_) + lane;
        cnt = T_;
        out_off = OFF_TOPIC + row * D_;
    } else if (row < ROWS_TOPIC + ROWS_PARA) {
        const int i = row - ROWS_TOPIC;
        const int* sp = para_spans + i * 3;
        src = (const float4*)(word_reps + ((size_t)sp[0] * L_ + sp[1]) * D_) + lane;
        cnt = sp[2] - sp[1] + 1;            // <= 256
        out_off = OFF_PARA + i * D_;
    } else if (row < ROWS_TOPIC + ROWS_PARA + ROWS_SHELL) {
        const int i = row - (ROWS_TOPIC + ROWS_PARA);
        const int* sp = shell_spans + i * 3;
        src = (const float4*)(word_reps + ((size_t)sp[0] * L_ + sp[1]) * D_) + lane;
        cnt = sp[2] - sp[1] + 1;            // <= 16
        out_off = OFF_SHELL + i * D_;
    } else {
        const int i = row - (ROWS_TOPIC + ROWS_PARA + ROWS_SHELL);
        const int* sp = x_spans + i * 3;
        src = (const float4*)(word_reps + ((size_t)sp[0] * L_ + sp[1]) * D_) + lane;
        cnt = sp[2] - sp[1] + 1;            // <= 64
        out_off = OFF_ADU + i * D_;
    }

    const float4 neg = make_float4(-FLT_MAX, -FLT_MAX, -FLT_MAX, -FLT_MAX);
    float4 acc = neg;

    // Slice ys pools rows ys, ys+8, ... in groups of 8 predicated independent
    // loads (64 rows/iteration). shell/topic/adu: 1 iter; para: <=4.
    #pragma unroll 1
    for (int r0 = ys; r0 < cnt; r0 += 8 * YS) {
        float4 v[8];
        #pragma unroll
        for (int j = 0; j < 8; j++) {
            const int r = r0 + j * YS;
            v[j] = (r < cnt) ? __ldg(src + (size_t)r * D4) : neg;
        }
        float4 a01 = f4max(v[0], v[1]);
        float4 a23 = f4max(v[2], v[3]);
        float4 a45 = f4max(v[4], v[5]);
        float4 a67 = f4max(v[6], v[7]);
        acc = f4max(acc, f4max(f4max(a01, a23), f4max(a45, a67)));
    }

    red[ys][lx] = acc;
    __syncthreads();                        // the only barrier

    if (ys == 0) {
        float4 r = f4max(f4max(f4max(red[0][lx], red[1][lx]),
                               f4max(red[2][lx], red[3][lx])),
                         f4max(f4max(red[4][lx], red[5][lx]),
                               f4max(red[6][lx], red[7][lx])));
        ((float4*)(out + out_off))[lane] = r;
    }
}

extern "C" void kernel_launch(void* const* d_in, const int* in_sizes, int n_in,
                              void* d_out, int out_size) {
    // metadata order: topic_reps, word_reps, topic_lens(int64, unused),
    //                 para_spans, x_spans, shell_spans
    const float* topic_reps  = (const float*)d_in[0];
    const float* word_reps   = (const float*)d_in[1];
    const int*   para_spans  = (const int*)d_in[3];
    const int*   x_spans     = (const int*)d_in[4];
    const int*   shell_spans = (const int*)d_in[5];
    float* out = (float*)d_out;

    dim3 block(32, YS);                // 256 threads
    dim3 grid(ROWS_TOTAL * 2);         // 912 blocks: (row, D-half)
    span_maxpool_dsplit_kernel<<<grid, block>>>(
        topic_reps, word_reps, para_spans, x_spans, shell_spans, out);
}